// round 1
// baseline (speedup 1.0000x reference)
#include <cuda_runtime.h>
#include <cuda_bf16.h>
#include <stdint.h>

// Problem constants (sized for the static scratch; runtime dims come from in_sizes)
#define MAX_USERS 100000
#define EMBED 128

// ---------------------------------------------------------------------------
// Scratch in __device__ globals (no allocation allowed anywhere)
// ---------------------------------------------------------------------------
__device__ float g_xt[(size_t)MAX_USERS * EMBED];   // x @ W result, 51.2 MB
__device__ int   g_row_ptr[MAX_USERS + 1];

// ---------------------------------------------------------------------------
// Copy layer-0 output: out[0] = user_embeds
// ---------------------------------------------------------------------------
__global__ void copy_kernel(float4* __restrict__ dst, const float4* __restrict__ src, int n4) {
    int i = blockIdx.x * blockDim.x + threadIdx.x;
    int stride = gridDim.x * blockDim.x;
    for (; i < n4; i += stride) dst[i] = src[i];
}

// ---------------------------------------------------------------------------
// Build CSR row_ptr from sorted s_rows
// ---------------------------------------------------------------------------
__global__ void build_rowptr_kernel(const int* __restrict__ rows, int E, int M) {
    int e = blockIdx.x * blockDim.x + threadIdx.x;
    if (e >= E) return;
    int r = rows[e];
    if (e == 0) {
        for (int i = 0; i <= r; i++) g_row_ptr[i] = 0;
    } else {
        int rp = rows[e - 1];
        for (int i = rp + 1; i <= r; i++) g_row_ptr[i] = e;
    }
    if (e == E - 1) {
        for (int i = r + 1; i <= M; i++) g_row_ptr[i] = E;
    }
}

// ---------------------------------------------------------------------------
// GEMM: g_xt = A[M,128] @ W[128,128]
// Block: 256 threads, 64 rows x 128 cols tile. Thread: 8 rows x 4 cols.
// Inner loop is FFMA-bound (32 FFMA vs 9 LDS per k-step per thread).
// ---------------------------------------------------------------------------
#define GM_TILE 64
#define GK_CHUNK 16

__global__ __launch_bounds__(256) void gemm_kernel(const float* __restrict__ A,
                                                   const float* __restrict__ W,
                                                   int M) {
    __shared__ float Ws[GK_CHUNK][EMBED];      // 16 x 128 f32 = 8 KB
    __shared__ float Xs[GM_TILE][GK_CHUNK];    // 64 x 16  f32 = 4 KB

    const int t   = threadIdx.x;
    const int cx  = t & 31;   // column group: cols [4*cx, 4*cx+4)
    const int ry  = t >> 5;   // row group 0..7: rows ry*8 .. ry*8+7
    const int row0 = blockIdx.x * GM_TILE;

    float4 acc[8];
#pragma unroll
    for (int i = 0; i < 8; i++) acc[i] = make_float4(0.f, 0.f, 0.f, 0.f);

    for (int kc = 0; kc < EMBED; kc += GK_CHUNK) {
        // Load W chunk: 16x128 floats = 512 float4, 256 threads -> 2 each
#pragma unroll
        for (int it = 0; it < 2; it++) {
            int idx = t + it * 256;            // 0..511
            int kk = idx >> 5;                 // /32
            int c4 = idx & 31;
            ((float4*)Ws[kk])[c4] = ((const float4*)(W + (size_t)(kc + kk) * EMBED))[c4];
        }
        // Load X chunk: 64 rows x 16 k = 256 float4, 1 per thread
        {
            int r  = t >> 2;
            int k4 = t & 3;
            int grow = row0 + r;
            float4 v = make_float4(0.f, 0.f, 0.f, 0.f);
            if (grow < M) v = ((const float4*)(A + (size_t)grow * EMBED + kc))[k4];
            ((float4*)Xs[r])[k4] = v;
        }
        __syncthreads();

#pragma unroll
        for (int kk = 0; kk < GK_CHUNK; kk++) {
            float4 w = ((float4*)Ws[kk])[cx];
#pragma unroll
            for (int i = 0; i < 8; i++) {
                float xv = Xs[ry * 8 + i][kk];
                acc[i].x += xv * w.x;
                acc[i].y += xv * w.y;
                acc[i].z += xv * w.z;
                acc[i].w += xv * w.w;
            }
        }
        __syncthreads();
    }

#pragma unroll
    for (int i = 0; i < 8; i++) {
        int r = row0 + ry * 8 + i;
        if (r < M) ((float4*)(g_xt + (size_t)r * EMBED))[cx] = acc[i];
    }
}

// ---------------------------------------------------------------------------
// SpMM + residual: out[r] = x[r] + sum_{e in row r} vals[e] * g_xt[cols[e]]
// One warp per row; lane owns a float4 (cols 4*lane..4*lane+3).
// ---------------------------------------------------------------------------
__global__ __launch_bounds__(256) void spmm_kernel(const float* __restrict__ x,
                                                   const int* __restrict__ cols,
                                                   const float* __restrict__ vals,
                                                   float* __restrict__ out,
                                                   int M) {
    int warp = (blockIdx.x * blockDim.x + threadIdx.x) >> 5;
    int lane = threadIdx.x & 31;
    if (warp >= M) return;
    int r = warp;
    int s = g_row_ptr[r];
    int e = g_row_ptr[r + 1];

    float4 acc = make_float4(0.f, 0.f, 0.f, 0.f);
    for (int base = s; base < e; base += 32) {
        int idx = base + lane;
        int   c = 0;
        float v = 0.f;
        if (idx < e) { c = __ldg(cols + idx); v = __ldg(vals + idx); }
        int cnt = min(32, e - base);
        for (int j = 0; j < cnt; j++) {
            int   cj = __shfl_sync(0xffffffffu, c, j);
            float vj = __shfl_sync(0xffffffffu, v, j);
            float4 t4 = ((const float4*)(g_xt + (size_t)cj * EMBED))[lane];
            acc.x += vj * t4.x;
            acc.y += vj * t4.y;
            acc.z += vj * t4.z;
            acc.w += vj * t4.w;
        }
    }
    float4 xv = ((const float4*)(x + (size_t)r * EMBED))[lane];
    acc.x += xv.x; acc.y += xv.y; acc.z += xv.z; acc.w += xv.w;
    ((float4*)(out + (size_t)r * EMBED))[lane] = acc;
}

// ---------------------------------------------------------------------------
// kernel_launch
// Inputs (metadata order): user_embeds[f32 M*128], s_rows[i32 E], s_cols[i32 E],
//                          s_values[f32 E], W0[f32 128*128], W1[f32 128*128]
// Output: [3, M, 128] f32
// ---------------------------------------------------------------------------
extern "C" void kernel_launch(void* const* d_in, const int* in_sizes, int n_in,
                              void* d_out, int out_size) {
    const float* ue   = (const float*)d_in[0];
    const int*   rows = (const int*)  d_in[1];
    const int*   cols = (const int*)  d_in[2];
    const float* vals = (const float*)d_in[3];
    const float* W0   = (const float*)d_in[4];
    const float* W1   = (const float*)d_in[5];
    float* out = (float*)d_out;

    const int M = in_sizes[0] / EMBED;
    const int E = in_sizes[1];
    const size_t layer_elems = (size_t)M * EMBED;

    // Layer 0 output = input embeddings
    {
        int n4 = (int)(layer_elems / 4);
        int blocks = (n4 + 255) / 256;
        if (blocks > 4096) blocks = 4096;
        copy_kernel<<<blocks, 256>>>((float4*)out, (const float4*)ue, n4);
    }

    // CSR row pointers (rows sorted)
    build_rowptr_kernel<<<(E + 255) / 256, 256>>>(rows, E, M);

    const int gemm_blocks = (M + GM_TILE - 1) / GM_TILE;
    const int spmm_blocks = (M * 32 + 255) / 256;

    // Layer 1
    gemm_kernel<<<gemm_blocks, 256>>>(ue, W0, M);
    spmm_kernel<<<spmm_blocks, 256>>>(ue, cols, vals, out + layer_elems, M);

    // Layer 2
    gemm_kernel<<<gemm_blocks, 256>>>(out + layer_elems, W1, M);
    spmm_kernel<<<spmm_blocks, 256>>>(out + layer_elems, cols, vals, out + 2 * layer_elems, M);
}

// round 2
// speedup vs baseline: 1.1209x; 1.1209x over previous
#include <cuda_runtime.h>
#include <cuda_bf16.h>
#include <stdint.h>

#define MAX_USERS 100000
#define EMBED 128

// ---------------------------------------------------------------------------
// Scratch in __device__ globals (no allocation allowed anywhere)
// ---------------------------------------------------------------------------
__device__ float g_xt[(size_t)MAX_USERS * EMBED];   // x @ W result, 51.2 MB
__device__ int   g_row_ptr[MAX_USERS + 1];

// ---------------------------------------------------------------------------
// f32x2 packed-FMA helpers (SASS FFMA2 — only reachable via PTX)
// ---------------------------------------------------------------------------
typedef unsigned long long ull;

union F2U { float2 f2; ull u; };

#define FMA2(d, a, b) \
    asm("fma.rn.f32x2 %0, %1, %2, %0;" : "+l"(d) : "l"(a), "l"(b))

#define PACKDUP(u, f) \
    asm("mov.b64 %0, {%1, %1};" : "=l"(u) : "f"(f))

#define UNPACK2(lo, hi, u) \
    asm("mov.b64 {%0, %1}, %2;" : "=f"(lo), "=f"(hi) : "l"(u))

// ---------------------------------------------------------------------------
// Build CSR row_ptr from sorted s_rows
// ---------------------------------------------------------------------------
__global__ void build_rowptr_kernel(const int* __restrict__ rows, int E, int M) {
    int e = blockIdx.x * blockDim.x + threadIdx.x;
    if (e >= E) return;
    int r = rows[e];
    if (e == 0) {
        for (int i = 0; i <= r; i++) g_row_ptr[i] = 0;
    } else {
        int rp = rows[e - 1];
        for (int i = rp + 1; i <= r; i++) g_row_ptr[i] = e;
    }
    if (e == E - 1) {
        for (int i = r + 1; i <= M; i++) g_row_ptr[i] = E;
    }
}

// ---------------------------------------------------------------------------
// GEMM via f32x2: g_xt = A[M,128] @ W[128,128]
// CTA: 256 threads, 64-row x 128-col tile. Thread: 8 rows (4 row-pairs) x 4 cols.
// acc pair packs {rowA, rowB}; A tile stored k-major (transposed) so a row-pair
// is a single LDS.64 (warp-uniform broadcast address).
// Double-buffered 16-k chunks, one __syncthreads per chunk.
// ---------------------------------------------------------------------------
#define GKC 16
#define XS_PAD 66   // floats per k-row in Xs: 64 rows + 2 pad (keeps 8B align, conflict-free stores)

__global__ __launch_bounds__(256) void gemm_f32x2_kernel(const float* __restrict__ A,
                                                         const float* __restrict__ W,
                                                         float* __restrict__ Xt,
                                                         int M) {
    __shared__ float Ws[2][GKC][EMBED];     // 2 x 8 KB
    __shared__ float Xs[2][GKC][XS_PAD];    // 2 x ~4.2 KB, layout [k][row]

    const int t  = threadIdx.x;
    const int cx = t & 31;    // column group: cols [4*cx, 4*cx+4)
    const int ry = t >> 5;    // row group 0..7: rows ry*8 .. ry*8+7 (4 pairs)
    const int row0 = blockIdx.x * 64;

    // loader mapping
    const int w_kk0 = t >> 5;          // chunk-k row for W load (first half)
    const int w_c4  = t & 31;          // float4 col for W load
    const int a_r   = t >> 2;          // row 0..63 for A load
    const int a_k4  = t & 3;           // k-quad 0..3 for A load

    ull acc[4][4];
#pragma unroll
    for (int p = 0; p < 4; p++)
#pragma unroll
        for (int c = 0; c < 4; c++) acc[p][c] = 0ull;

    float4 wreg0, wreg1, areg;

    // prefetch chunk 0
    {
        wreg0 = ((const float4*)(W + (size_t)(w_kk0) * EMBED))[w_c4];
        wreg1 = ((const float4*)(W + (size_t)(w_kk0 + 8) * EMBED))[w_c4];
        int grow = row0 + a_r;
        areg = make_float4(0.f, 0.f, 0.f, 0.f);
        if (grow < M) areg = ((const float4*)(A + (size_t)grow * EMBED))[a_k4];
    }
    // store chunk 0
    {
        ((float4*)Ws[0][w_kk0])[w_c4] = wreg0;
        ((float4*)Ws[0][w_kk0 + 8])[w_c4] = wreg1;
        Xs[0][a_k4 * 4 + 0][a_r] = areg.x;
        Xs[0][a_k4 * 4 + 1][a_r] = areg.y;
        Xs[0][a_k4 * 4 + 2][a_r] = areg.z;
        Xs[0][a_k4 * 4 + 3][a_r] = areg.w;
    }
    __syncthreads();

    const int NCHUNK = EMBED / GKC;   // 8
#pragma unroll 1
    for (int c = 0; c < NCHUNK; c++) {
        const int buf = c & 1;
        // issue global loads for next chunk (overlap with compute)
        if (c < NCHUNK - 1) {
            int kc = (c + 1) * GKC;
            wreg0 = ((const float4*)(W + (size_t)(kc + w_kk0) * EMBED))[w_c4];
            wreg1 = ((const float4*)(W + (size_t)(kc + w_kk0 + 8) * EMBED))[w_c4];
            int grow = row0 + a_r;
            areg = make_float4(0.f, 0.f, 0.f, 0.f);
            if (grow < M) areg = ((const float4*)(A + (size_t)grow * EMBED + kc))[a_k4];
        }

        // compute on current buffer
#pragma unroll
        for (int k = 0; k < GKC; k++) {
            float4 w = ((float4*)Ws[buf][k])[cx];
            ull wp0, wp1, wp2, wp3;
            PACKDUP(wp0, w.x);
            PACKDUP(wp1, w.y);
            PACKDUP(wp2, w.z);
            PACKDUP(wp3, w.w);
#pragma unroll
            for (int p = 0; p < 4; p++) {
                F2U a;
                a.f2 = *(const float2*)&Xs[buf][k][ry * 8 + 2 * p];
                FMA2(acc[p][0], a.u, wp0);
                FMA2(acc[p][1], a.u, wp1);
                FMA2(acc[p][2], a.u, wp2);
                FMA2(acc[p][3], a.u, wp3);
            }
        }

        // store next chunk to other buffer
        if (c < NCHUNK - 1) {
            int nb = buf ^ 1;
            ((float4*)Ws[nb][w_kk0])[w_c4] = wreg0;
            ((float4*)Ws[nb][w_kk0 + 8])[w_c4] = wreg1;
            Xs[nb][a_k4 * 4 + 0][a_r] = areg.x;
            Xs[nb][a_k4 * 4 + 1][a_r] = areg.y;
            Xs[nb][a_k4 * 4 + 2][a_r] = areg.z;
            Xs[nb][a_k4 * 4 + 3][a_r] = areg.w;
            __syncthreads();
        }
    }

    // write out: pair p holds rows (row0+ry*8+2p) [lo] and +1 [hi], cols 4*cx..+3
#pragma unroll
    for (int p = 0; p < 4; p++) {
        float4 lo4, hi4;
        UNPACK2(lo4.x, hi4.x, acc[p][0]);
        UNPACK2(lo4.y, hi4.y, acc[p][1]);
        UNPACK2(lo4.z, hi4.z, acc[p][2]);
        UNPACK2(lo4.w, hi4.w, acc[p][3]);
        int rA = row0 + ry * 8 + 2 * p;
        int rB = rA + 1;
        if (rA < M) ((float4*)(Xt + (size_t)rA * EMBED))[cx] = lo4;
        if (rB < M) ((float4*)(Xt + (size_t)rB * EMBED))[cx] = hi4;
    }
}

// ---------------------------------------------------------------------------
// SpMM + residual: out[r] = x[r] + sum_{e in row r} vals[e] * g_xt[cols[e]]
// One warp per row; lane owns a float4. Optionally also writes out0[r] = x[r]
// (fuses the layer-0 copy into the layer-1 SpMM for free: x[r] is loaded anyway)
// ---------------------------------------------------------------------------
__global__ __launch_bounds__(256) void spmm_kernel(const float* __restrict__ x,
                                                   const int* __restrict__ cols,
                                                   const float* __restrict__ vals,
                                                   float* __restrict__ out,
                                                   float* __restrict__ out0,
                                                   int M) {
    int warp = (blockIdx.x * blockDim.x + threadIdx.x) >> 5;
    int lane = threadIdx.x & 31;
    if (warp >= M) return;
    int r = warp;
    int s = g_row_ptr[r];
    int e = g_row_ptr[r + 1];

    float4 acc = make_float4(0.f, 0.f, 0.f, 0.f);
    for (int base = s; base < e; base += 32) {
        int idx = base + lane;
        int   c = 0;
        float v = 0.f;
        if (idx < e) { c = __ldg(cols + idx); v = __ldg(vals + idx); }
        int cnt = min(32, e - base);
        for (int j = 0; j < cnt; j++) {
            int   cj = __shfl_sync(0xffffffffu, c, j);
            float vj = __shfl_sync(0xffffffffu, v, j);
            float4 t4 = ((const float4*)(g_xt + (size_t)cj * EMBED))[lane];
            acc.x += vj * t4.x;
            acc.y += vj * t4.y;
            acc.z += vj * t4.z;
            acc.w += vj * t4.w;
        }
    }
    float4 xv = ((const float4*)(x + (size_t)r * EMBED))[lane];
    if (out0) ((float4*)(out0 + (size_t)r * EMBED))[lane] = xv;
    acc.x += xv.x; acc.y += xv.y; acc.z += xv.z; acc.w += xv.w;
    ((float4*)(out + (size_t)r * EMBED))[lane] = acc;
}

// ---------------------------------------------------------------------------
// kernel_launch
// Inputs: user_embeds[f32 M*128], s_rows[i32 E], s_cols[i32 E],
//         s_values[f32 E], W0[f32 128*128], W1[f32 128*128]
// Output: [3, M, 128] f32
// ---------------------------------------------------------------------------
extern "C" void kernel_launch(void* const* d_in, const int* in_sizes, int n_in,
                              void* d_out, int out_size) {
    const float* ue   = (const float*)d_in[0];
    const int*   rows = (const int*)  d_in[1];
    const int*   cols = (const int*)  d_in[2];
    const float* vals = (const float*)d_in[3];
    const float* W0   = (const float*)d_in[4];
    const float* W1   = (const float*)d_in[5];
    float* out = (float*)d_out;

    const int M = in_sizes[0] / EMBED;
    const int E = in_sizes[1];
    const size_t layer_elems = (size_t)M * EMBED;

    float* xt_ptr;
    cudaGetSymbolAddress((void**)&xt_ptr, g_xt);

    // CSR row pointers (rows sorted)
    build_rowptr_kernel<<<(E + 255) / 256, 256>>>(rows, E, M);

    const int gemm_blocks = (M + 63) / 64;
    const int spmm_blocks = (M * 32 + 255) / 256;

    // Layer 1 (SpMM also emits out[0] = user_embeds)
    gemm_f32x2_kernel<<<gemm_blocks, 256>>>(ue, W0, xt_ptr, M);
    spmm_kernel<<<spmm_blocks, 256>>>(ue, cols, vals, out + layer_elems, out, M);

    // Layer 2
    gemm_f32x2_kernel<<<gemm_blocks, 256>>>(out + layer_elems, W1, xt_ptr, M);
    spmm_kernel<<<spmm_blocks, 256>>>(out + layer_elems, cols, vals,
                                      out + 2 * layer_elems, nullptr, M);
}